// round 1
// baseline (speedup 1.0000x reference)
#include <cuda_runtime.h>
#include <math.h>

#define NQ   10
#define DIM  1024      // 2^NQ
#define NP   64
#define DF   10
#define NL   5

// Scratch (no allocations allowed) --------------------------------------
__device__ float2 g_states[NP * DIM];   // psi(x_p) for each point, 512 KB
__device__ float  g_K[NP * NP];         // |<psi_j|psi_i>|^2

// ------------------------------------------------------------------------
// Kernel 1: simulate psi(x_p) = Prod_layers block_f |0>  (one block per point)
// block_f: H on all qubits, rz diag, ry on all qubits, crz-ring diag.
// ------------------------------------------------------------------------
__global__ __launch_bounds__(512) void sim_kernel(
    const float* __restrict__ data,     // (NP, DF)
    const float* __restrict__ params)   // (NL, 2, NQ)
{
    __shared__ float sre[DIM];
    __shared__ float sim_[DIM];
    __shared__ float xs[NQ];        // feature vector of this point
    __shared__ float ry_c[NQ], ry_s[NQ], ring_phi[NQ];

    const int p = blockIdx.x;
    const int t = threadIdx.x;      // 512 threads

    if (t < NQ) xs[t] = data[p * DF + t];
    #pragma unroll
    for (int e = 0; e < 2; ++e) {
        int idx = t + e * 512;
        sre[idx] = (idx == 0) ? 1.f : 0.f;
        sim_[idx] = 0.f;
    }
    __syncthreads();

    const float INV_S2 = 0.70710678118654752440f;

    for (int layer = 0; layer < NL; ++layer) {
        // ---- H on every qubit (butterfly; pairs partition the state) ----
        #pragma unroll
        for (int q = 0; q < NQ; ++q) {
            int i0 = ((t >> q) << (q + 1)) | (t & ((1 << q) - 1));
            int i1 = i0 | (1 << q);
            float r0 = sre[i0], r1 = sre[i1];
            float m0 = sim_[i0], m1 = sim_[i1];
            sre[i0] = (r0 + r1) * INV_S2;  sre[i1] = (r0 - r1) * INV_S2;
            sim_[i0] = (m0 + m1) * INV_S2;  sim_[i1] = (m0 - m1) * INV_S2;
            __syncthreads();
        }

        // ---- rz diagonal: phase = sum_q (b_q - 1/2) * x[9-q] ----
        #pragma unroll
        for (int e = 0; e < 2; ++e) {
            int idx = t + e * 512;
            float ang = 0.f;
            #pragma unroll
            for (int q = 0; q < NQ; ++q)
                ang += (((idx >> q) & 1) ? 0.5f : -0.5f) * xs[NQ - 1 - q];
            float s, c;
            sincosf(ang, &s, &c);
            float r = sre[idx], m = sim_[idx];
            sre[idx] = r * c - m * s;
            sim_[idx] = r * s + m * c;
        }

        // load this layer's ry + ring params while others finish the diag
        if (t < NQ) {
            float a = 0.5f * params[layer * 2 * NQ + t];
            ry_c[t] = cosf(a);
            ry_s[t] = sinf(a);
            ring_phi[t] = params[layer * 2 * NQ + NQ + t];
        }
        __syncthreads();

        // ---- ry on every qubit: [[c,-s],[s,c]] ----
        #pragma unroll
        for (int q = 0; q < NQ; ++q) {
            int i0 = ((t >> q) << (q + 1)) | (t & ((1 << q) - 1));
            int i1 = i0 | (1 << q);
            float c = ry_c[q], s = ry_s[q];
            float r0 = sre[i0], r1 = sre[i1];
            float m0 = sim_[i0], m1 = sim_[i1];
            sre[i0] = c * r0 - s * r1;  sre[i1] = s * r0 + c * r1;
            sim_[i0] = c * m0 - s * m1; sim_[i1] = s * m0 + c * m1;
            __syncthreads();
        }

        // ---- crz ring diagonal: phase = sum_m b_m * (b_{(m+1)%10} - 1/2) * phi_m ----
        #pragma unroll
        for (int e = 0; e < 2; ++e) {
            int idx = t + e * 512;
            float ang = 0.f;
            #pragma unroll
            for (int m = 0; m < NQ; ++m) {
                int tg = (m + 1 == NQ) ? 0 : m + 1;
                if ((idx >> m) & 1)
                    ang += (((idx >> tg) & 1) ? 0.5f : -0.5f) * ring_phi[m];
            }
            float s, c;
            sincosf(ang, &s, &c);
            float r = sre[idx], m = sim_[idx];
            sre[idx] = r * c - m * s;
            sim_[idx] = r * s + m * c;
        }
        __syncthreads();
    }

    // write out
    #pragma unroll
    for (int e = 0; e < 2; ++e) {
        int idx = t + e * 512;
        g_states[p * DIM + idx] = make_float2(sre[idx], sim_[idx]);
    }
}

// ------------------------------------------------------------------------
// Kernel 2: K[i,j] = |<psi_j | psi_i>|^2, one block per (i,j)
// ------------------------------------------------------------------------
__global__ __launch_bounds__(256) void gram_kernel()
{
    const int j = blockIdx.x;   // x2 index (tile)
    const int i = blockIdx.y;   // x1 index (repeat)
    const float2* __restrict__ a = g_states + i * DIM;   // psi(x1)
    const float2* __restrict__ b = g_states + j * DIM;   // psi(x2)

    float re = 0.f, im = 0.f;
    #pragma unroll
    for (int k = threadIdx.x; k < DIM; k += 256) {
        float2 av = a[k], bv = b[k];
        re += bv.x * av.x + bv.y * av.y;   // conj(b) * a
        im += bv.x * av.y - bv.y * av.x;
    }
    // warp reduce
    #pragma unroll
    for (int off = 16; off; off >>= 1) {
        re += __shfl_down_sync(0xffffffffu, re, off);
        im += __shfl_down_sync(0xffffffffu, im, off);
    }
    __shared__ float sr[8], si[8];
    int lane = threadIdx.x & 31, wid = threadIdx.x >> 5;
    if (lane == 0) { sr[wid] = re; si[wid] = im; }
    __syncthreads();
    if (threadIdx.x == 0) {
        float R = 0.f, I = 0.f;
        #pragma unroll
        for (int w = 0; w < 8; ++w) { R += sr[w]; I += si[w]; }
        g_K[i * NP + j] = R * R + I * I;
    }
}

// ------------------------------------------------------------------------
// Kernel 3: KTA = sum(lm*K) / sqrt(sum(K*K) * sum(lm*lm)),  lm = l_i*l_j
// Deterministic single-block double reduction.
// ------------------------------------------------------------------------
__global__ __launch_bounds__(256) void finalize_kernel(
    const float* __restrict__ labels, float* __restrict__ out)
{
    __shared__ double skp[256];
    __shared__ double skk[256];
    const int t = threadIdx.x;

    double kp = 0.0, kk = 0.0;
    for (int pidx = t; pidx < NP * NP; pidx += 256) {
        int i = pidx >> 6, j = pidx & 63;
        double k = (double)g_K[pidx];
        double lm = (double)labels[i] * (double)labels[j];
        kp += lm * k;
        kk += k * k;
    }
    skp[t] = kp; skk[t] = kk;
    __syncthreads();
    for (int s = 128; s; s >>= 1) {
        if (t < s) { skp[t] += skp[t + s]; skk[t] += skk[t + s]; }
        __syncthreads();
    }
    if (t == 0) {
        double sl2 = 0.0;
        for (int i = 0; i < NP; ++i) {
            double l = (double)labels[i];
            sl2 += l * l;
        }
        double lm2 = sl2 * sl2;   // sum over pairs of (l_i*l_j)^2
        out[0] = (float)(skp[0] / sqrt(skk[0] * lm2));
    }
}

// ------------------------------------------------------------------------
extern "C" void kernel_launch(void* const* d_in, const int* in_sizes, int n_in,
                              void* d_out, int out_size)
{
    const float* data   = (const float*)d_in[0];   // (64, 10)
    const float* labels = (const float*)d_in[1];   // (64,)
    const float* params = (const float*)d_in[2];   // (5, 2, 10)
    float* out = (float*)d_out;

    sim_kernel<<<NP, 512>>>(data, params);
    gram_kernel<<<dim3(NP, NP), 256>>>();
    finalize_kernel<<<1, 256>>>(labels, out);
}

// round 2
// speedup vs baseline: 1.2049x; 1.2049x over previous
#include <cuda_runtime.h>
#include <math.h>

#define NQ   10
#define DIM  1024
#define NP   64
#define DF   10
#define NL   5

#define TWOPI   6.2831853071795864769f
#define INV2PI  0.15915494309189533577f

// Scratch (no allocations allowed)
__device__ float2 g_states[NP * DIM];   // psi(x_p), 512 KB
__device__ float  g_K[NP * NP];

// ------------------------------------------------------------------------
// Kernel 1: simulate psi(x_p). One block (128 threads) per point.
// Amplitude index = (r<<7) | t : r in [0,8) register slot (qubits 7-9),
// t = threadIdx (bits 0-4 = lane -> qubits 0-4, bits 5-6 = warp -> qubits 5-6).
// H normalization (1/sqrt2)^10 per layer folded (exactly, 2^-5) into the
// layer-invariant rz diagonal factors, which are precomputed once.
// ------------------------------------------------------------------------
__global__ __launch_bounds__(128) void sim_kernel(
    const float* __restrict__ data,     // (NP, DF)
    const float* __restrict__ params)   // (NL, 2, NQ)
{
    __shared__ float xs[16];                    // xs[q] = x[9-q]
    __shared__ float ryc[NL][NQ], rys[NL][NQ], phi[NL][NQ];
    __shared__ float sbuf[2][128 * 17];         // padded exchange buffers

    const int p    = blockIdx.x;
    const int t    = threadIdx.x;
    const int lane = t & 31;
    const int w    = t >> 5;
    const int b5   = w & 1;
    const int b6   = (w >> 1) & 1;

    if (t < NQ) xs[t] = data[p * DF + (NQ - 1 - t)];
    if (t < NL * NQ) {
        int l = t / NQ, m = t % NQ;
        float s, c;
        sincosf(0.5f * params[l * 2 * NQ + m], &s, &c);
        ryc[l][m] = c;  rys[l][m] = s;
        phi[l][m] = params[l * 2 * NQ + NQ + m];
    }
    __syncthreads();

    // state in registers
    float re[8], im[8];
    #pragma unroll
    for (int r = 0; r < 8; ++r) { re[r] = 0.f; im[r] = 0.f; }
    if (t == 0) re[0] = 1.f;

    // precompute rz diagonal factors (identical in every layer), * 2^-5
    float rzc[8], rzs[8];
    {
        float base = 0.f;
        #pragma unroll
        for (int q = 0; q < NQ; ++q) base -= 0.5f * xs[q];
        #pragma unroll
        for (int q = 0; q < 7; ++q) if ((t >> q) & 1) base += xs[q];
        #pragma unroll
        for (int r = 0; r < 8; ++r) {
            float ang = base;
            if (r & 1) ang += xs[7];
            if (r & 2) ang += xs[8];
            if (r & 4) ang += xs[9];
            ang = fmaf(-TWOPI, rintf(ang * INV2PI), ang);
            float s, c;
            __sincosf(ang, &s, &c);
            rzc[r] = c * 0.03125f;
            rzs[r] = s * 0.03125f;
        }
    }

    const float b6f = (float)((t >> 6) & 1);
    const float bt0 = (t & 1) ? 0.5f : -0.5f;

    #pragma unroll 1
    for (int l = 0; l < NL; ++l) {
        // ---- H on qubits 0-4 (shfl butterflies, unnormalized) ----
        #pragma unroll
        for (int q = 0; q < 5; ++q) {
            float sgn = ((lane >> q) & 1) ? -1.f : 1.f;
            #pragma unroll
            for (int r = 0; r < 8; ++r) {
                float o = __shfl_xor_sync(0xffffffffu, re[r], 1 << q);
                re[r] = fmaf(sgn, re[r], o);
                o = __shfl_xor_sync(0xffffffffu, im[r], 1 << q);
                im[r] = fmaf(sgn, im[r], o);
            }
        }
        // ---- H on qubits 7-9 (in-register) ----
        #pragma unroll
        for (int b = 0; b < 3; ++b) {
            int m = 1 << b;
            #pragma unroll
            for (int r = 0; r < 8; ++r) {
                if (!(r & m)) {
                    int r1 = r | m;
                    float a = re[r], bb = re[r1];
                    re[r] = a + bb;  re[r1] = a - bb;
                    a = im[r];  bb = im[r1];
                    im[r] = a + bb;  im[r1] = a - bb;
                }
            }
        }
        // ---- H on qubits 5,6: combined 4-way cross-warp exchange ----
        {
            float* sb = sbuf[0];
            float* my = sb + t * 17;
            #pragma unroll
            for (int r = 0; r < 8; ++r) { my[r] = re[r]; my[r + 8] = im[r]; }
            __syncthreads();
            float sgnv[4];
            #pragma unroll
            for (int pw = 0; pw < 4; ++pw)
                sgnv[pw] = ((b5 & (pw & 1)) ^ (b6 & ((pw >> 1) & 1))) ? -1.f : 1.f;
            #pragma unroll
            for (int r = 0; r < 8; ++r) {
                float accR = 0.f, accI = 0.f;
                #pragma unroll
                for (int pw = 0; pw < 4; ++pw) {
                    const float* pr = sb + (lane + (pw << 5)) * 17;
                    accR = fmaf(sgnv[pw], pr[r],     accR);
                    accI = fmaf(sgnv[pw], pr[r + 8], accI);
                }
                re[r] = accR;  im[r] = accI;
            }
        }
        // ---- rz diagonal (precomputed, includes 2^-5) ----
        #pragma unroll
        for (int r = 0; r < 8; ++r) {
            float nr = re[r] * rzc[r] - im[r] * rzs[r];
            im[r]    = re[r] * rzs[r] + im[r] * rzc[r];
            re[r]    = nr;
        }
        // ---- RY on qubits 0-4 (shfl) ----
        #pragma unroll
        for (int q = 0; q < 5; ++q) {
            float c  = ryc[l][q];
            float ss = ((lane >> q) & 1) ? rys[l][q] : -rys[l][q];
            #pragma unroll
            for (int r = 0; r < 8; ++r) {
                float o = __shfl_xor_sync(0xffffffffu, re[r], 1 << q);
                re[r] = fmaf(c, re[r], ss * o);
                o = __shfl_xor_sync(0xffffffffu, im[r], 1 << q);
                im[r] = fmaf(c, im[r], ss * o);
            }
        }
        // ---- RY on qubits 7-9 (in-register) ----
        #pragma unroll
        for (int b = 0; b < 3; ++b) {
            float c = ryc[l][7 + b], s = rys[l][7 + b];
            int m = 1 << b;
            #pragma unroll
            for (int r = 0; r < 8; ++r) {
                if (!(r & m)) {
                    int r1 = r | m;
                    float a0 = re[r], a1 = re[r1];
                    re[r]  = c * a0 - s * a1;
                    re[r1] = s * a0 + c * a1;
                    a0 = im[r];  a1 = im[r1];
                    im[r]  = c * a0 - s * a1;
                    im[r1] = s * a0 + c * a1;
                }
            }
        }
        // ---- RY on qubits 5,6: combined cross-warp exchange ----
        {
            float* sb = sbuf[1];
            float* my = sb + t * 17;
            #pragma unroll
            for (int r = 0; r < 8; ++r) { my[r] = re[r]; my[r + 8] = im[r]; }
            __syncthreads();
            float c5 = ryc[l][5], s5 = rys[l][5];
            float c6 = ryc[l][6], s6 = rys[l][6];
            float m5[2], m6[2];
            m5[b5] = c5;  m5[b5 ^ 1] = b5 ? s5 : -s5;
            m6[b6] = c6;  m6[b6 ^ 1] = b6 ? s6 : -s6;
            float coef[4];
            #pragma unroll
            for (int pw = 0; pw < 4; ++pw)
                coef[pw] = m5[pw & 1] * m6[(pw >> 1) & 1];
            #pragma unroll
            for (int r = 0; r < 8; ++r) {
                float accR = 0.f, accI = 0.f;
                #pragma unroll
                for (int pw = 0; pw < 4; ++pw) {
                    const float* pr = sb + (lane + (pw << 5)) * 17;
                    accR = fmaf(coef[pw], pr[r],     accR);
                    accI = fmaf(coef[pw], pr[r + 8], accI);
                }
                re[r] = accR;  im[r] = accI;
            }
        }
        // ---- crz ring diagonal ----
        {
            float angT = 0.f;
            #pragma unroll
            for (int m = 0; m < 6; ++m) {
                if ((t >> m) & 1) {
                    float bt = ((t >> (m + 1)) & 1) ? 0.5f : -0.5f;
                    angT += bt * phi[l][m];
                }
            }
            #pragma unroll
            for (int r = 0; r < 8; ++r) {
                const float fb7 = (float)(r & 1);
                const float fb8 = (float)((r >> 1) & 1);
                const float fb9 = (float)((r >> 2) & 1);
                float ang = angT;
                ang += b6f * (fb7 - 0.5f) * phi[l][6];
                ang += fb7 * (fb8 - 0.5f) * phi[l][7];
                ang += fb8 * (fb9 - 0.5f) * phi[l][8];
                ang += fb9 * bt0 * phi[l][9];
                ang = fmaf(-TWOPI, rintf(ang * INV2PI), ang);
                float s, c;
                __sincosf(ang, &s, &c);
                float nr = re[r] * c - im[r] * s;
                im[r]    = re[r] * s + im[r] * c;
                re[r]    = nr;
            }
        }
    }

    #pragma unroll
    for (int r = 0; r < 8; ++r)
        g_states[p * DIM + (r << 7) + t] = make_float2(re[r], im[r]);
}

// ------------------------------------------------------------------------
// Kernel 2: K[i,j] = |<psi_j|psi_i>|^2. 8x8 pair tile per block,
// 2x2 register sub-tiles, k staged through shared in 4 chunks of 256.
// ------------------------------------------------------------------------
__global__ __launch_bounds__(256) void gram_kernel()
{
    __shared__ float2 As[8][256];
    __shared__ float2 Bs[8][256];

    const int t  = threadIdx.x;
    const int i0 = blockIdx.y * 8, j0 = blockIdx.x * 8;
    const int g  = t >> 4;          // 16 groups -> 4x4 grid of 2x2 sub-tiles
    const int ks = t & 15;          // k-slice within group (half-warp aligned)
    const int py = (g >> 2) * 2;
    const int px = (g & 3) * 2;

    float aR[2][2] = {{0.f,0.f},{0.f,0.f}};
    float aI[2][2] = {{0.f,0.f},{0.f,0.f}};

    for (int kc = 0; kc < 4; ++kc) {
        const int kb = kc * 256;
        #pragma unroll
        for (int ld = 0; ld < 8; ++ld) {
            int idx = t + ld * 256;
            int row = idx >> 8, col = idx & 255;
            As[row][col] = g_states[(i0 + row) * DIM + kb + col];
            Bs[row][col] = g_states[(j0 + row) * DIM + kb + col];
        }
        __syncthreads();
        #pragma unroll 4
        for (int k = ks; k < 256; k += 16) {
            float2 a0 = As[py][k],     a1 = As[py + 1][k];
            float2 b0 = Bs[px][k],     b1 = Bs[px + 1][k];
            // conj(b) * a
            aR[0][0] += b0.x*a0.x + b0.y*a0.y;  aI[0][0] += b0.x*a0.y - b0.y*a0.x;
            aR[0][1] += b1.x*a0.x + b1.y*a0.y;  aI[0][1] += b1.x*a0.y - b1.y*a0.x;
            aR[1][0] += b0.x*a1.x + b0.y*a1.y;  aI[1][0] += b0.x*a1.y - b0.y*a1.x;
            aR[1][1] += b1.x*a1.x + b1.y*a1.y;  aI[1][1] += b1.x*a1.y - b1.y*a1.x;
        }
        __syncthreads();
    }

    #pragma unroll
    for (int off = 8; off; off >>= 1) {
        #pragma unroll
        for (int di = 0; di < 2; ++di)
            #pragma unroll
            for (int dj = 0; dj < 2; ++dj) {
                aR[di][dj] += __shfl_down_sync(0xffffffffu, aR[di][dj], off, 16);
                aI[di][dj] += __shfl_down_sync(0xffffffffu, aI[di][dj], off, 16);
            }
    }
    if (ks == 0) {
        #pragma unroll
        for (int di = 0; di < 2; ++di)
            #pragma unroll
            for (int dj = 0; dj < 2; ++dj) {
                float R = aR[di][dj], I = aI[di][dj];
                g_K[(i0 + py + di) * NP + (j0 + px + dj)] = R * R + I * I;
            }
    }
}

// ------------------------------------------------------------------------
// Kernel 3: KTA = sum(lm*K) / sqrt(sum(K*K) * sum(lm*lm))
// ------------------------------------------------------------------------
__global__ __launch_bounds__(256) void finalize_kernel(
    const float* __restrict__ labels, float* __restrict__ out)
{
    __shared__ double skp[256];
    __shared__ double skk[256];
    const int t = threadIdx.x;

    double kp = 0.0, kk = 0.0;
    for (int pidx = t; pidx < NP * NP; pidx += 256) {
        int i = pidx >> 6, j = pidx & 63;
        double k  = (double)g_K[pidx];
        double lm = (double)labels[i] * (double)labels[j];
        kp += lm * k;
        kk += k * k;
    }
    skp[t] = kp;  skk[t] = kk;
    __syncthreads();
    for (int s = 128; s; s >>= 1) {
        if (t < s) { skp[t] += skp[t + s]; skk[t] += skk[t + s]; }
        __syncthreads();
    }
    if (t == 0) {
        double sl2 = 0.0;
        for (int i = 0; i < NP; ++i) {
            double l = (double)labels[i];
            sl2 += l * l;
        }
        out[0] = (float)(skp[0] / sqrt(skk[0] * sl2 * sl2));
    }
}

// ------------------------------------------------------------------------
extern "C" void kernel_launch(void* const* d_in, const int* in_sizes, int n_in,
                              void* d_out, int out_size)
{
    const float* data   = (const float*)d_in[0];   // (64, 10)
    const float* labels = (const float*)d_in[1];   // (64,)
    const float* params = (const float*)d_in[2];   // (5, 2, 10)
    float* out = (float*)d_out;

    sim_kernel<<<NP, 128>>>(data, params);
    gram_kernel<<<dim3(8, 8), 256>>>();
    finalize_kernel<<<1, 256>>>(labels, out);
}